// round 14
// baseline (speedup 1.0000x reference)
#include <cuda_runtime.h>
#include <cuda_bf16.h>
#include <cuda_fp16.h>
#include <cstdint>

#define NNODES 100000
#define NEDGES 1600000
#define DIM    128
#define OUTD   32
#define NGRAPH 512
#define NLAYER 3
#define NMAT   6          // enc1, enc2, gcn0, gcn1, gcn2, dec1
#define NBLK   ((NNODES + 255) / 256)   // 391 scan blocks

// ---------------- scratch (static __device__ — no allocation allowed) -------
__device__ __half g_h   [NNODES * DIM];   // fp16 activations (relu'd h)
__device__ __half g_hwh [NNODES * DIM];   // fp16 h@W (gather payload)
__device__ float  g_inv [NNODES];
__device__ float  g_pool[NGRAPH * DIM];
__device__ float  g_dec1[NGRAPH * DIM];
__device__ int    g_cnt [NNODES];
__device__ int    g_off [NNODES + 1];
__device__ int    g_cur [NNODES];
__device__ int    g_bsum[NBLK];
__device__ int    g_bpre[NBLK];
__device__ int    g_gstart[NGRAPH + 1];
__device__ int2   g_csr [NEDGES];          // {src, bits(inv[src])} binned by dst
// weight images, B-operand layout: Bimg[n][k] = W[k][n], linear [n*128+k]
__device__ __nv_bfloat16 g_whi[NMAT * DIM * DIM];   // bf16 hi (fp32-A path)
__device__ __nv_bfloat16 g_wlo[NMAT * DIM * DIM];   // bf16 lo
__device__ __half        g_w16h[NMAT * DIM * DIM];  // fp16 hi (fp16-A path)
__device__ __half        g_w16l[NMAT * DIM * DIM];  // fp16 lo residual

// ==================== helpers ===============================================
__device__ __forceinline__ uint32_t smem_u32(const void* p) {
    uint32_t a;
    asm("{ .reg .u64 t; cvta.to.shared.u64 t, %1; cvt.u32.u64 %0, t; }"
        : "=r"(a) : "l"(p));
    return a;
}

__device__ __forceinline__ void ldsm4(uint32_t* r, uint32_t addr) {
    asm volatile("ldmatrix.sync.aligned.m8n8.x4.shared.b16 {%0,%1,%2,%3}, [%4];"
                 : "=r"(r[0]), "=r"(r[1]), "=r"(r[2]), "=r"(r[3]) : "r"(addr));
}

__device__ __forceinline__ void mma_bf16(float* c, const uint32_t* a,
                                         uint32_t b0, uint32_t b1) {
    asm volatile(
        "mma.sync.aligned.m16n8k16.row.col.f32.bf16.bf16.f32 "
        "{%0,%1,%2,%3}, {%4,%5,%6,%7}, {%8,%9}, {%0,%1,%2,%3};"
        : "+f"(c[0]), "+f"(c[1]), "+f"(c[2]), "+f"(c[3])
        : "r"(a[0]), "r"(a[1]), "r"(a[2]), "r"(a[3]), "r"(b0), "r"(b1));
}

__device__ __forceinline__ void mma_f16(float* c, const uint32_t* a,
                                        uint32_t b0, uint32_t b1) {
    asm volatile(
        "mma.sync.aligned.m16n8k16.row.col.f32.f16.f16.f32 "
        "{%0,%1,%2,%3}, {%4,%5,%6,%7}, {%8,%9}, {%0,%1,%2,%3};"
        : "+f"(c[0]), "+f"(c[1]), "+f"(c[2]), "+f"(c[3])
        : "r"(a[0]), "r"(a[1]), "r"(a[2]), "r"(a[3]), "r"(b0), "r"(b1));
}

// pack two fp32 into bf16x2 hi image + lo residual image
__device__ __forceinline__ void split2(float x, float y, uint32_t& hi, uint32_t& lo) {
    const __nv_bfloat16 hx = __float2bfloat16_rn(x);
    const __nv_bfloat16 hy = __float2bfloat16_rn(y);
    const __nv_bfloat16 lx = __float2bfloat16_rn(x - __bfloat162float(hx));
    const __nv_bfloat16 ly = __float2bfloat16_rn(y - __bfloat162float(hy));
    hi = ((uint32_t)__bfloat16_as_ushort(hy) << 16) | __bfloat16_as_ushort(hx);
    lo = ((uint32_t)__bfloat16_as_ushort(ly) << 16) | __bfloat16_as_ushort(lx);
}

// ==================== weight prep ===========================================
struct WPtrs { const float* w[NMAT]; };

__global__ void prepw_kernel(WPtrs wp) {
    const int mat = blockIdx.x >> 6;
    const int i0  = (blockIdx.x & 63) * 256 + threadIdx.x;   // = n*128+k
    const float* W = wp.w[mat];
    const int n = i0 >> 7, k = i0 & 127;
    const float w = W[k * DIM + n];
    // bf16 hi/lo (fp32-A path)
    const __nv_bfloat16 h = __float2bfloat16_rn(w);
    const __nv_bfloat16 l = __float2bfloat16_rn(w - __bfloat162float(h));
    g_whi[mat * DIM * DIM + i0] = h;
    g_wlo[mat * DIM * DIM + i0] = l;
    // fp16 hi/lo (fp16-A path)
    const __half h16 = __float2half_rn(w);
    const __half l16 = __float2half_rn(w - __half2float(h16));
    g_w16h[mat * DIM * DIM + i0] = h16;
    g_w16l[mat * DIM * DIM + i0] = l16;
}

// ==================== CSR build =============================================
__global__ void hist_kernel(const int* __restrict__ dst, int E) {
    int e = blockIdx.x * blockDim.x + threadIdx.x;
    if (e < E) atomicAdd(&g_cnt[dst[e]], 1);
}

__global__ void invsqrt_kernel(int n) {
    int i = blockIdx.x * blockDim.x + threadIdx.x;
    if (i < n) g_inv[i] = rsqrtf((float)g_cnt[i] + 1.0f);
}

__global__ void blocksum_kernel() {
    __shared__ int ss[256];
    const int t = threadIdx.x;
    const int i = blockIdx.x * 256 + t;
    ss[t] = (i < NNODES) ? g_cnt[i] : 0;
    __syncthreads();
    #pragma unroll
    for (int d = 128; d > 0; d >>= 1) {
        if (t < d) ss[t] += ss[t + d];
        __syncthreads();
    }
    if (t == 0) g_bsum[blockIdx.x] = ss[0];
}

__global__ void bscan_kernel() {
    __shared__ int ss[512];
    const int t = threadIdx.x;
    const int v = (t < NBLK) ? g_bsum[t] : 0;
    ss[t] = v;
    __syncthreads();
    #pragma unroll
    for (int d = 1; d < 512; d <<= 1) {
        int u = (t >= d) ? ss[t - d] : 0;
        __syncthreads();
        ss[t] += u;
        __syncthreads();
    }
    if (t < NBLK) g_bpre[t] = ss[t] - v;
    if (t == NBLK - 1) g_off[NNODES] = ss[t];
}

__global__ void offsets_kernel() {
    __shared__ int ss[256];
    const int t = threadIdx.x;
    const int i = blockIdx.x * 256 + t;
    const int v = (i < NNODES) ? g_cnt[i] : 0;
    ss[t] = v;
    __syncthreads();
    #pragma unroll
    for (int d = 1; d < 256; d <<= 1) {
        int u = (t >= d) ? ss[t - d] : 0;
        __syncthreads();
        ss[t] += u;
        __syncthreads();
    }
    if (i < NNODES) {
        const int excl = ss[t] - v + g_bpre[blockIdx.x];
        g_off[i] = excl;
        g_cur[i] = excl;
    }
}

__global__ void bin_kernel(const int* __restrict__ src,
                           const int* __restrict__ dst, int E) {
    int e = blockIdx.x * blockDim.x + threadIdx.x;
    if (e >= E) return;
    const int s = src[e], d = dst[e];
    const int pos = atomicAdd(&g_cur[d], 1);
    g_csr[pos] = make_int2(s, __float_as_int(g_inv[s]));
}

// ==================== shared GEMM geometry ===================================
#define TSTRIDE 272                 // bytes per padded B row (136 halves)
#define TILE_B  (128 * TSTRIDE)     // 34816
#define BH_OFF  1024
#define BL_OFF  (BH_OFF + TILE_B)
#define SMEM_BYTES (BL_OFF + TILE_B)   // 70656

// ==================== fp32-A GEMM (3-pass bf16 split): enc1 / dec1 ==========
// OUTH=true: outh(fp16) = relu(C+b);  OUTH=false: outf(fp32) = relu(C+b)
template <bool OUTH>
__global__ __launch_bounds__(256, 2)
void mmagemm_kernel(const float* __restrict__ A,
                    const __nv_bfloat16* __restrict__ Whi,
                    const __nv_bfloat16* __restrict__ Wlo,
                    const float* __restrict__ bias,
                    float* __restrict__ outf,
                    __half* __restrict__ outh,
                    int nrows)
{
    extern __shared__ char smem[];
    const uint32_t sbase = smem_u32(smem);
    const int tid  = threadIdx.x;
    const int wid  = tid >> 5;
    const int lane = tid & 31;
    const int row0 = blockIdx.x * 128;
    const int rvalid = min(nrows - row0, 128);

    if (tid < 128) ((float*)smem)[tid] = bias[tid];
    {
        const float4* sh = (const float4*)Whi;
        const float4* sl = (const float4*)Wlo;
        #pragma unroll
        for (int it = 0; it < 8; it++) {
            const int idx = tid + 256 * it;
            const int r = idx >> 4, c = idx & 15;
            *(float4*)(smem + BH_OFF + r * TSTRIDE + c * 16) = sh[idx];
            *(float4*)(smem + BL_OFF + r * TSTRIDE + c * 16) = sl[idx];
        }
    }
    __syncthreads();

    const int warp_m = wid & 3;
    const int warp_n = wid >> 2;
    const int gid = lane >> 2;
    const int tig = lane & 3;

    const int base = row0 + warp_m * 32 + gid;
    const float* rA0 = A + (size_t)min(base +  0, nrows - 1) * DIM + tig * 2;
    const float* rA1 = A + (size_t)min(base +  8, nrows - 1) * DIM + tig * 2;
    const float* rA2 = A + (size_t)min(base + 16, nrows - 1) * DIM + tig * 2;
    const float* rA3 = A + (size_t)min(base + 24, nrows - 1) * DIM + tig * 2;

    const uint32_t b_off = (uint32_t)(warp_n * 64 + (lane & 7) + (lane >> 4) * 8) * TSTRIDE
                         + (uint32_t)((lane >> 3) & 1) * 16;
    const uint32_t b_hi = sbase + BH_OFF + b_off;
    const uint32_t b_lo = sbase + BL_OFF + b_off;

    float acc[2][8][4];
    #pragma unroll
    for (int i = 0; i < 2; i++)
        #pragma unroll
        for (int j = 0; j < 8; j++)
            #pragma unroll
            for (int q = 0; q < 4; q++) acc[i][j][q] = 0.f;

    #pragma unroll
    for (int kc = 0; kc < 8; kc++) {
        const int c0 = kc * 16;
        float2 v[8];
        v[0] = *(const float2*)(rA0 + c0);
        v[1] = *(const float2*)(rA1 + c0);
        v[2] = *(const float2*)(rA2 + c0);
        v[3] = *(const float2*)(rA3 + c0);
        v[4] = *(const float2*)(rA0 + c0 + 8);
        v[5] = *(const float2*)(rA1 + c0 + 8);
        v[6] = *(const float2*)(rA2 + c0 + 8);
        v[7] = *(const float2*)(rA3 + c0 + 8);
        uint32_t ah0[4], ah1[4], al0[4], al1[4];
        split2(v[0].x, v[0].y, ah0[0], al0[0]);
        split2(v[1].x, v[1].y, ah0[1], al0[1]);
        split2(v[4].x, v[4].y, ah0[2], al0[2]);
        split2(v[5].x, v[5].y, ah0[3], al0[3]);
        split2(v[2].x, v[2].y, ah1[0], al1[0]);
        split2(v[3].x, v[3].y, ah1[1], al1[1]);
        split2(v[6].x, v[6].y, ah1[2], al1[2]);
        split2(v[7].x, v[7].y, ah1[3], al1[3]);

        const uint32_t kb = (uint32_t)kc * 32;
        #pragma unroll
        for (int g = 0; g < 4; g++) {
            uint32_t bh[4], bl[4];
            ldsm4(bh, b_hi + (uint32_t)g * 16 * TSTRIDE + kb);
            ldsm4(bl, b_lo + (uint32_t)g * 16 * TSTRIDE + kb);
            const int n0 = 2 * g, n1 = 2 * g + 1;
            mma_bf16(acc[0][n0], ah0, bh[0], bh[1]);
            mma_bf16(acc[0][n1], ah0, bh[2], bh[3]);
            mma_bf16(acc[1][n0], ah1, bh[0], bh[1]);
            mma_bf16(acc[1][n1], ah1, bh[2], bh[3]);
            mma_bf16(acc[0][n0], ah0, bl[0], bl[1]);
            mma_bf16(acc[0][n1], ah0, bl[2], bl[3]);
            mma_bf16(acc[1][n0], ah1, bl[0], bl[1]);
            mma_bf16(acc[1][n1], ah1, bl[2], bl[3]);
            mma_bf16(acc[0][n0], al0, bh[0], bh[1]);
            mma_bf16(acc[0][n1], al0, bh[2], bh[3]);
            mma_bf16(acc[1][n0], al1, bh[0], bh[1]);
            mma_bf16(acc[1][n1], al1, bh[2], bh[3]);
        }
    }

    __syncthreads();   // in-place safety (A may alias out)

    const float* sbias = (const float*)smem;
    #pragma unroll
    for (int mt = 0; mt < 2; mt++) {
        #pragma unroll
        for (int h = 0; h < 2; h++) {
            const int rloc = warp_m * 32 + mt * 16 + h * 8 + gid;
            if (rloc >= rvalid) continue;
            const int r = row0 + rloc;
            #pragma unroll
            for (int nt = 0; nt < 8; nt++) {
                const int col = warp_n * 64 + nt * 8 + 2 * tig;
                const float c0 = fmaxf(acc[mt][nt][h * 2 + 0] + sbias[col],     0.f);
                const float c1 = fmaxf(acc[mt][nt][h * 2 + 1] + sbias[col + 1], 0.f);
                if (OUTH)
                    *(__half2*)(outh + (size_t)r * DIM + col) = __floats2half2_rn(c0, c1);
                else
                    *(float2*)(outf + (size_t)r * DIM + col) = make_float2(c0, c1);
            }
        }
    }
}

// ==================== fp16-A GEMM (2-pass fp16 W split): enc2 / gcn ==========
// OUTMODE 0: out = relu(C+b) fp16 ; OUTMODE 1: out = C fp16 (raw, for hwh)
template <int OUTMODE>
__global__ __launch_bounds__(256, 2)
void mmagemm16_kernel(const __half* __restrict__ A,
                      const __half* __restrict__ Whi,
                      const __half* __restrict__ Wlo,
                      const float* __restrict__ bias,
                      __half* __restrict__ out,
                      int nrows)
{
    extern __shared__ char smem[];
    const uint32_t sbase = smem_u32(smem);
    const int tid  = threadIdx.x;
    const int wid  = tid >> 5;
    const int lane = tid & 31;
    const int row0 = blockIdx.x * 128;
    const int rvalid = min(nrows - row0, 128);

    if (OUTMODE == 0 && tid < 128) ((float*)smem)[tid] = bias[tid];
    {
        const float4* sh = (const float4*)Whi;
        const float4* sl = (const float4*)Wlo;
        #pragma unroll
        for (int it = 0; it < 8; it++) {
            const int idx = tid + 256 * it;
            const int r = idx >> 4, c = idx & 15;
            *(float4*)(smem + BH_OFF + r * TSTRIDE + c * 16) = sh[idx];
            *(float4*)(smem + BL_OFF + r * TSTRIDE + c * 16) = sl[idx];
        }
    }
    __syncthreads();

    const int warp_m = wid & 3;
    const int warp_n = wid >> 2;
    const int gid = lane >> 2;
    const int tig = lane & 3;

    const int base = row0 + warp_m * 32 + gid;
    const __half* rA0 = A + (size_t)min(base +  0, nrows - 1) * DIM + tig * 2;
    const __half* rA1 = A + (size_t)min(base +  8, nrows - 1) * DIM + tig * 2;
    const __half* rA2 = A + (size_t)min(base + 16, nrows - 1) * DIM + tig * 2;
    const __half* rA3 = A + (size_t)min(base + 24, nrows - 1) * DIM + tig * 2;

    const uint32_t b_off = (uint32_t)(warp_n * 64 + (lane & 7) + (lane >> 4) * 8) * TSTRIDE
                         + (uint32_t)((lane >> 3) & 1) * 16;
    const uint32_t b_hi = sbase + BH_OFF + b_off;
    const uint32_t b_lo = sbase + BL_OFF + b_off;

    float acc[2][8][4];
    #pragma unroll
    for (int i = 0; i < 2; i++)
        #pragma unroll
        for (int j = 0; j < 8; j++)
            #pragma unroll
            for (int q = 0; q < 4; q++) acc[i][j][q] = 0.f;

    #pragma unroll
    for (int kc = 0; kc < 8; kc++) {
        const int c0 = kc * 16;
        // A fragments: direct uint32 loads of 2 halves (exact fp16, no conversion)
        uint32_t ah0[4], ah1[4];
        ah0[0] = *(const uint32_t*)(rA0 + c0);
        ah0[1] = *(const uint32_t*)(rA1 + c0);
        ah0[2] = *(const uint32_t*)(rA0 + c0 + 8);
        ah0[3] = *(const uint32_t*)(rA1 + c0 + 8);
        ah1[0] = *(const uint32_t*)(rA2 + c0);
        ah1[1] = *(const uint32_t*)(rA3 + c0);
        ah1[2] = *(const uint32_t*)(rA2 + c0 + 8);
        ah1[3] = *(const uint32_t*)(rA3 + c0 + 8);

        const uint32_t kb = (uint32_t)kc * 32;
        #pragma unroll
        for (int g = 0; g < 4; g++) {
            uint32_t bh[4], bl[4];
            ldsm4(bh, b_hi + (uint32_t)g * 16 * TSTRIDE + kb);
            ldsm4(bl, b_lo + (uint32_t)g * 16 * TSTRIDE + kb);
            const int n0 = 2 * g, n1 = 2 * g + 1;
            mma_f16(acc[0][n0], ah0, bh[0], bh[1]);
            mma_f16(acc[0][n1], ah0, bh[2], bh[3]);
            mma_f16(acc[1][n0], ah1, bh[0], bh[1]);
            mma_f16(acc[1][n1], ah1, bh[2], bh[3]);
            mma_f16(acc[0][n0], ah0, bl[0], bl[1]);
            mma_f16(acc[0][n1], ah0, bl[2], bl[3]);
            mma_f16(acc[1][n0], ah1, bl[0], bl[1]);
            mma_f16(acc[1][n1], ah1, bl[2], bl[3]);
        }
    }

    __syncthreads();   // in-place safety (enc2: A aliases out)

    const float* sbias = (const float*)smem;
    #pragma unroll
    for (int mt = 0; mt < 2; mt++) {
        #pragma unroll
        for (int h = 0; h < 2; h++) {
            const int rloc = warp_m * 32 + mt * 16 + h * 8 + gid;
            if (rloc >= rvalid) continue;
            const int r = row0 + rloc;
            #pragma unroll
            for (int nt = 0; nt < 8; nt++) {
                const int col = warp_n * 64 + nt * 8 + 2 * tig;
                float c0 = acc[mt][nt][h * 2 + 0];
                float c1 = acc[mt][nt][h * 2 + 1];
                if (OUTMODE == 0) {
                    c0 = fmaxf(c0 + sbias[col],     0.f);
                    c1 = fmaxf(c1 + sbias[col + 1], 0.f);
                }
                *(__half2*)(out + (size_t)r * DIM + col) = __floats2half2_rn(c0, c1);
            }
        }
    }
}

// ==================== gather: h = relu(agg) computed + stored fp16 ===========
// h[n] = relu( inv[n]*Σ_{e∈CSR[n]} inv_s*hw16[s] + inv[n]^2*hw16[n] + b )
__global__ __launch_bounds__(256)
void gather_kernel(const __half* __restrict__ hwh, __half* __restrict__ hout,
                   const float* __restrict__ bias)
{
    const int node = (blockIdx.x * blockDim.x + threadIdx.x) >> 5;
    const int lane = threadIdx.x & 31;
    if (node >= NNODES) return;
    const int e0 = g_off[node];
    const int e1 = g_off[node + 1];

    float4 acc = make_float4(0.f, 0.f, 0.f, 0.f);
    int e = e0;
    for (; e + 2 <= e1; e += 2) {
        const int2 sw0 = g_csr[e];
        const int2 sw1 = g_csr[e + 1];
        const uint2 u0 = *((const uint2*)(hwh + (size_t)sw0.x * DIM) + lane);
        const uint2 u1 = *((const uint2*)(hwh + (size_t)sw1.x * DIM) + lane);
        const float w0 = __int_as_float(sw0.y);
        const float w1 = __int_as_float(sw1.y);
        float2 a0 = __half22float2(*(const __half2*)&u0.x);
        float2 b0 = __half22float2(*(const __half2*)&u0.y);
        float2 a1 = __half22float2(*(const __half2*)&u1.x);
        float2 b1 = __half22float2(*(const __half2*)&u1.y);
        acc.x = fmaf(a0.x, w0, acc.x); acc.y = fmaf(a0.y, w0, acc.y);
        acc.z = fmaf(b0.x, w0, acc.z); acc.w = fmaf(b0.y, w0, acc.w);
        acc.x = fmaf(a1.x, w1, acc.x); acc.y = fmaf(a1.y, w1, acc.y);
        acc.z = fmaf(b1.x, w1, acc.z); acc.w = fmaf(b1.y, w1, acc.w);
    }
    if (e < e1) {
        const int2 sw = g_csr[e];
        const uint2 u0 = *((const uint2*)(hwh + (size_t)sw.x * DIM) + lane);
        const float w = __int_as_float(sw.y);
        float2 a0 = __half22float2(*(const __half2*)&u0.x);
        float2 b0 = __half22float2(*(const __half2*)&u0.y);
        acc.x = fmaf(a0.x, w, acc.x); acc.y = fmaf(a0.y, w, acc.y);
        acc.z = fmaf(b0.x, w, acc.z); acc.w = fmaf(b0.y, w, acc.w);
    }

    const float invd = g_inv[node];
    const float sc   = invd * invd;
    const uint2 us = *((const uint2*)(hwh + (size_t)node * DIM) + lane);
    const float2 s0 = __half22float2(*(const __half2*)&us.x);
    const float2 s1 = __half22float2(*(const __half2*)&us.y);
    const float4 b  = *((const float4*)bias + lane);

    float4 a;
    a.x = fmaxf(fmaf(acc.x, invd, fmaf(s0.x, sc, b.x)), 0.f);
    a.y = fmaxf(fmaf(acc.y, invd, fmaf(s0.y, sc, b.y)), 0.f);
    a.z = fmaxf(fmaf(acc.z, invd, fmaf(s1.x, sc, b.z)), 0.f);
    a.w = fmaxf(fmaf(acc.w, invd, fmaf(s1.y, sc, b.w)), 0.f);
    const __half2 p0 = __floats2half2_rn(a.x, a.y);
    const __half2 p1 = __floats2half2_rn(a.z, a.w);
    uint2 st;
    st.x = *(const uint32_t*)&p0;
    st.y = *(const uint32_t*)&p1;
    *((uint2*)(hout + (size_t)node * DIM) + lane) = st;   // pure store
}

// ==================== pool: segment sums over fp16 h =========================
__global__ void gstart_kernel(const int* __restrict__ batch, int N) {
    const int g = blockIdx.x * blockDim.x + threadIdx.x;
    if (g > NGRAPH) return;
    if (g == NGRAPH) { g_gstart[NGRAPH] = N; return; }
    int lo = 0, hi = N;
    while (lo < hi) {
        int mid = (lo + hi) >> 1;
        if (batch[mid] < g) lo = mid + 1; else hi = mid;
    }
    g_gstart[g] = lo;
}

__global__ __launch_bounds__(128)
void pool_kernel(const __half* __restrict__ h)
{
    const int g = blockIdx.x;
    const int c = threadIdx.x;
    const int lo = g_gstart[g];
    const int hi = g_gstart[g + 1];
    float s = 0.f;
    for (int i = lo; i < hi; i++)
        s += __half2float(h[(size_t)i * DIM + c]);
    g_pool[(size_t)g * DIM + c] = s;
}

__global__ void dec2_kernel(const float* __restrict__ dec1,
                            const float* __restrict__ W2,
                            const float* __restrict__ b2,
                            float* __restrict__ out)
{
    const int idx = blockIdx.x * blockDim.x + threadIdx.x;
    if (idx >= NGRAPH * OUTD) return;
    const int g = idx >> 5;
    const int o = idx & 31;
    const float* row = dec1 + (size_t)g * DIM;
    float s = b2[o];
    #pragma unroll 8
    for (int k = 0; k < DIM; k++) s = fmaf(row[k], W2[k * OUTD + o], s);
    out[idx] = s;
}

// ==================== host launch ===========================================
extern "C" void kernel_launch(void* const* d_in, const int* in_sizes, int n_in,
                              void* d_out, int out_size)
{
    const float* x       = (const float*)d_in[0];
    const int*   eidx    = (const int*)  d_in[1];
    const int*   batch   = (const int*)  d_in[2];
    const float* enc_W1  = (const float*)d_in[3];
    const float* enc_b1  = (const float*)d_in[4];
    const float* enc_W2  = (const float*)d_in[5];
    const float* enc_b2  = (const float*)d_in[6];
    const float* gcn_W   = (const float*)d_in[7];
    const float* gcn_b   = (const float*)d_in[8];
    const float* dec_W1  = (const float*)d_in[9];
    const float* dec_b1  = (const float*)d_in[10];
    const float* dec_W2  = (const float*)d_in[11];
    const float* dec_b2  = (const float*)d_in[12];

    const int N = in_sizes[0] / DIM;
    const int E = in_sizes[1] / 2;
    const int* src = eidx;
    const int* dst = eidx + E;

    float *poolp, *dec1p;
    __half *hp, *hwhp, *w16hp, *w16lp;
    int* cntp;
    __nv_bfloat16 *whip, *wlop;
    cudaGetSymbolAddress((void**)&hp,    g_h);
    cudaGetSymbolAddress((void**)&hwhp,  g_hwh);
    cudaGetSymbolAddress((void**)&poolp, g_pool);
    cudaGetSymbolAddress((void**)&dec1p, g_dec1);
    cudaGetSymbolAddress((void**)&cntp,  g_cnt);
    cudaGetSymbolAddress((void**)&whip,  g_whi);
    cudaGetSymbolAddress((void**)&wlop,  g_wlo);
    cudaGetSymbolAddress((void**)&w16hp, g_w16h);
    cudaGetSymbolAddress((void**)&w16lp, g_w16l);

    cudaFuncSetAttribute(mmagemm_kernel<true>,
                         cudaFuncAttributeMaxDynamicSharedMemorySize, SMEM_BYTES);
    cudaFuncSetAttribute(mmagemm_kernel<false>,
                         cudaFuncAttributeMaxDynamicSharedMemorySize, SMEM_BYTES);
    cudaFuncSetAttribute(mmagemm16_kernel<0>,
                         cudaFuncAttributeMaxDynamicSharedMemorySize, SMEM_BYTES);
    cudaFuncSetAttribute(mmagemm16_kernel<1>,
                         cudaFuncAttributeMaxDynamicSharedMemorySize, SMEM_BYTES);

    const int WSZ = DIM * DIM;
    const int gemm_blocks = (N + 127) / 128;

    // Fork a side stream for the CSR chain (independent of prep + encoder).
    cudaStream_t s2;
    cudaStreamCreateWithFlags(&s2, cudaStreamNonBlocking);
    cudaEvent_t ev_fork, ev_join;
    cudaEventCreateWithFlags(&ev_fork, cudaEventDisableTiming);
    cudaEventCreateWithFlags(&ev_join, cudaEventDisableTiming);

    cudaEventRecord(ev_fork, 0);
    cudaStreamWaitEvent(s2, ev_fork, 0);

    // ---- s2: CSR build + degree normalization + pool segment starts ----
    cudaMemsetAsync(cntp, 0, NNODES * sizeof(int), s2);
    hist_kernel<<<(E + 255) / 256, 256, 0, s2>>>(dst, E);
    invsqrt_kernel<<<(N + 255) / 256, 256, 0, s2>>>(N);
    blocksum_kernel<<<NBLK, 256, 0, s2>>>();
    bscan_kernel<<<1, 512, 0, s2>>>();
    offsets_kernel<<<NBLK, 256, 0, s2>>>();
    bin_kernel<<<(E + 255) / 256, 256, 0, s2>>>(src, dst, E);
    gstart_kernel<<<3, 256, 0, s2>>>(batch, N);
    cudaEventRecord(ev_join, s2);

    // ---- main stream: weight prep + encoder MLP ----
    {
        WPtrs wp;
        wp.w[0] = enc_W1; wp.w[1] = enc_W2;
        wp.w[2] = gcn_W;  wp.w[3] = gcn_W + WSZ; wp.w[4] = gcn_W + 2 * WSZ;
        wp.w[5] = dec_W1;
        prepw_kernel<<<NMAT * 64, 256>>>(wp);
    }
    // enc1: fp32 A (x) -> fp16 h
    mmagemm_kernel<true><<<gemm_blocks, 256, SMEM_BYTES>>>(
        x, whip + 0 * WSZ, wlop + 0 * WSZ, enc_b1, nullptr, hp, N);
    // enc2: fp16 A -> fp16 h (in place; sync-guarded)
    mmagemm16_kernel<0><<<gemm_blocks, 256, SMEM_BYTES>>>(
        hp, w16hp + 1 * WSZ, w16lp + 1 * WSZ, enc_b2, hp, N);

    // join: GCN gather needs g_inv/g_csr
    cudaStreamWaitEvent(0, ev_join, 0);

    // ---- GCN layers: fp16 GEMM -> hwh; gather computes relu'd h (pure store)
    const int gather_blocks = (NNODES * 32 + 255) / 256;
    for (int l = 0; l < NLAYER; l++) {
        mmagemm16_kernel<1><<<gemm_blocks, 256, SMEM_BYTES>>>(
            hp, w16hp + (2 + l) * WSZ, w16lp + (2 + l) * WSZ,
            nullptr, hwhp, N);
        gather_kernel<<<gather_blocks, 256>>>(hwhp, hp, gcn_b + (size_t)l * DIM);
    }

    // ---- global add pool + decoder ----
    pool_kernel<<<NGRAPH, 128>>>(hp);
    mmagemm_kernel<false><<<(NGRAPH + 127) / 128, 256, SMEM_BYTES>>>(
        poolp, whip + 5 * WSZ, wlop + 5 * WSZ, dec_b1, dec1p, nullptr, NGRAPH);
    dec2_kernel<<<(NGRAPH * OUTD + 255) / 256, 256>>>(dec1p, dec_W2, dec_b2, (float*)d_out);
}

// round 17
// speedup vs baseline: 1.3676x; 1.3676x over previous
#include <cuda_runtime.h>
#include <cuda_bf16.h>
#include <cuda_fp16.h>
#include <cstdint>

#define NNODES 100000
#define NEDGES 1600000
#define DIM    128
#define OUTD   32
#define NGRAPH 512
#define NLAYER 3
#define NMAT   6          // enc1, enc2, gcn0, gcn1, gcn2, dec1
#define NBLK   ((NNODES + 255) / 256)   // 391 scan blocks

// ---------------- scratch (static __device__ — no allocation allowed) -------
__device__ __half g_h   [NNODES * DIM];   // fp16 activations (relu'd h)
__device__ __half g_hwh [NNODES * DIM];   // fp16 h@W (gather payload)
__device__ float  g_inv [NNODES];
__device__ float  g_pool[NGRAPH * DIM];
__device__ float  g_dec1[NGRAPH * DIM];
__device__ int    g_cnt [NNODES];
__device__ int    g_off [NNODES + 1];
__device__ int    g_cur [NNODES];
__device__ int    g_bsum[NBLK];
__device__ int    g_bpre[NBLK];
__device__ int    g_gstart[NGRAPH + 1];
__device__ int2   g_csr [NEDGES];          // {src, bits(inv[src])} binned by dst
// bf16 weight images, B-operand layout: Bimg[n][k] = W[k][n], linear [n*128+k]
__device__ __nv_bfloat16 g_whi[NMAT * DIM * DIM];
__device__ __nv_bfloat16 g_wlo[NMAT * DIM * DIM];

// ==================== helpers ===============================================
__device__ __forceinline__ uint32_t smem_u32(const void* p) {
    uint32_t a;
    asm("{ .reg .u64 t; cvta.to.shared.u64 t, %1; cvt.u32.u64 %0, t; }"
        : "=r"(a) : "l"(p));
    return a;
}

__device__ __forceinline__ void ldsm4(uint32_t* r, uint32_t addr) {
    asm volatile("ldmatrix.sync.aligned.m8n8.x4.shared.b16 {%0,%1,%2,%3}, [%4];"
                 : "=r"(r[0]), "=r"(r[1]), "=r"(r[2]), "=r"(r[3]) : "r"(addr));
}

__device__ __forceinline__ void mma_bf16(float* c, const uint32_t* a,
                                         uint32_t b0, uint32_t b1) {
    asm volatile(
        "mma.sync.aligned.m16n8k16.row.col.f32.bf16.bf16.f32 "
        "{%0,%1,%2,%3}, {%4,%5,%6,%7}, {%8,%9}, {%0,%1,%2,%3};"
        : "+f"(c[0]), "+f"(c[1]), "+f"(c[2]), "+f"(c[3])
        : "r"(a[0]), "r"(a[1]), "r"(a[2]), "r"(a[3]), "r"(b0), "r"(b1));
}

// pack two fp32 into bf16x2 hi image + lo residual image (exact 2-term split)
__device__ __forceinline__ void split2(float x, float y, uint32_t& hi, uint32_t& lo) {
    const __nv_bfloat16 hx = __float2bfloat16_rn(x);
    const __nv_bfloat16 hy = __float2bfloat16_rn(y);
    const __nv_bfloat16 lx = __float2bfloat16_rn(x - __bfloat162float(hx));
    const __nv_bfloat16 ly = __float2bfloat16_rn(y - __bfloat162float(hy));
    hi = ((uint32_t)__bfloat16_as_ushort(hy) << 16) | __bfloat16_as_ushort(hx);
    lo = ((uint32_t)__bfloat16_as_ushort(ly) << 16) | __bfloat16_as_ushort(lx);
}

// fp16 pair (packed u32) -> bf16 hi/lo images (fp16 splits into bf16 hi+lo exactly)
__device__ __forceinline__ void split2h(uint32_t hpair, uint32_t& hi, uint32_t& lo) {
    const float2 f = __half22float2(*(const __half2*)&hpair);
    split2(f.x, f.y, hi, lo);
}

// ==================== weight prep: fp32 W -> bf16 hi/lo transposed images ====
struct WPtrs { const float* w[NMAT]; };

__global__ void prepw_kernel(WPtrs wp) {
    const int mat = blockIdx.x >> 6;
    const int i0  = (blockIdx.x & 63) * 256 + threadIdx.x;   // = n*128+k
    const float* W = wp.w[mat];
    const int n = i0 >> 7, k = i0 & 127;
    const float w = W[k * DIM + n];
    const __nv_bfloat16 h = __float2bfloat16_rn(w);
    const __nv_bfloat16 l = __float2bfloat16_rn(w - __bfloat162float(h));
    g_whi[mat * DIM * DIM + i0] = h;
    g_wlo[mat * DIM * DIM + i0] = l;
}

// ==================== CSR build =============================================
__global__ void hist_kernel(const int* __restrict__ dst, int E) {
    int e = blockIdx.x * blockDim.x + threadIdx.x;
    if (e < E) atomicAdd(&g_cnt[dst[e]], 1);
}

__global__ void invsqrt_kernel(int n) {
    int i = blockIdx.x * blockDim.x + threadIdx.x;
    if (i < n) g_inv[i] = rsqrtf((float)g_cnt[i] + 1.0f);
}

__global__ void blocksum_kernel() {
    __shared__ int ss[256];
    const int t = threadIdx.x;
    const int i = blockIdx.x * 256 + t;
    ss[t] = (i < NNODES) ? g_cnt[i] : 0;
    __syncthreads();
    #pragma unroll
    for (int d = 128; d > 0; d >>= 1) {
        if (t < d) ss[t] += ss[t + d];
        __syncthreads();
    }
    if (t == 0) g_bsum[blockIdx.x] = ss[0];
}

__global__ void bscan_kernel() {
    __shared__ int ss[512];
    const int t = threadIdx.x;
    const int v = (t < NBLK) ? g_bsum[t] : 0;
    ss[t] = v;
    __syncthreads();
    #pragma unroll
    for (int d = 1; d < 512; d <<= 1) {
        int u = (t >= d) ? ss[t - d] : 0;
        __syncthreads();
        ss[t] += u;
        __syncthreads();
    }
    if (t < NBLK) g_bpre[t] = ss[t] - v;
    if (t == NBLK - 1) g_off[NNODES] = ss[t];
}

__global__ void offsets_kernel() {
    __shared__ int ss[256];
    const int t = threadIdx.x;
    const int i = blockIdx.x * 256 + t;
    const int v = (i < NNODES) ? g_cnt[i] : 0;
    ss[t] = v;
    __syncthreads();
    #pragma unroll
    for (int d = 1; d < 256; d <<= 1) {
        int u = (t >= d) ? ss[t - d] : 0;
        __syncthreads();
        ss[t] += u;
        __syncthreads();
    }
    if (i < NNODES) {
        const int excl = ss[t] - v + g_bpre[blockIdx.x];
        g_off[i] = excl;
        g_cur[i] = excl;
    }
}

__global__ void bin_kernel(const int* __restrict__ src,
                           const int* __restrict__ dst, int E) {
    int e = blockIdx.x * blockDim.x + threadIdx.x;
    if (e >= E) return;
    const int s = src[e], d = dst[e];
    const int pos = atomicAdd(&g_cur[d], 1);
    g_csr[pos] = make_int2(s, __float_as_int(g_inv[s]));
}

// ==================== shared GEMM geometry ===================================
#define TSTRIDE 272                 // bytes per padded B row (136 bf16)
#define TILE_B  (128 * TSTRIDE)     // 34816
#define BH_OFF  1024
#define BL_OFF  (BH_OFF + TILE_B)
#define SMEM_BYTES (BL_OFF + TILE_B)   // 70656

// ==================== fp32-A GEMM (3-pass bf16): enc1 / dec1 =================
// OUTH=true: outh(fp16) = relu(C+b);  OUTH=false: outf(fp32) = relu(C+b)
template <bool OUTH>
__global__ __launch_bounds__(256, 2)
void mmagemm_kernel(const float* __restrict__ A,
                    const __nv_bfloat16* __restrict__ Whi,
                    const __nv_bfloat16* __restrict__ Wlo,
                    const float* __restrict__ bias,
                    float* __restrict__ outf,
                    __half* __restrict__ outh,
                    int nrows)
{
    extern __shared__ char smem[];
    const uint32_t sbase = smem_u32(smem);
    const int tid  = threadIdx.x;
    const int wid  = tid >> 5;
    const int lane = tid & 31;
    const int row0 = blockIdx.x * 128;
    const int rvalid = min(nrows - row0, 128);

    if (tid < 128) ((float*)smem)[tid] = bias[tid];
    {
        const float4* sh = (const float4*)Whi;
        const float4* sl = (const float4*)Wlo;
        #pragma unroll
        for (int it = 0; it < 8; it++) {
            const int idx = tid + 256 * it;
            const int r = idx >> 4, c = idx & 15;
            *(float4*)(smem + BH_OFF + r * TSTRIDE + c * 16) = sh[idx];
            *(float4*)(smem + BL_OFF + r * TSTRIDE + c * 16) = sl[idx];
        }
    }
    __syncthreads();

    const int warp_m = wid & 3;
    const int warp_n = wid >> 2;
    const int gid = lane >> 2;
    const int tig = lane & 3;

    const int base = row0 + warp_m * 32 + gid;
    const float* rA0 = A + (size_t)min(base +  0, nrows - 1) * DIM + tig * 2;
    const float* rA1 = A + (size_t)min(base +  8, nrows - 1) * DIM + tig * 2;
    const float* rA2 = A + (size_t)min(base + 16, nrows - 1) * DIM + tig * 2;
    const float* rA3 = A + (size_t)min(base + 24, nrows - 1) * DIM + tig * 2;

    const uint32_t b_off = (uint32_t)(warp_n * 64 + (lane & 7) + (lane >> 4) * 8) * TSTRIDE
                         + (uint32_t)((lane >> 3) & 1) * 16;
    const uint32_t b_hi = sbase + BH_OFF + b_off;
    const uint32_t b_lo = sbase + BL_OFF + b_off;

    float acc[2][8][4];
    #pragma unroll
    for (int i = 0; i < 2; i++)
        #pragma unroll
        for (int j = 0; j < 8; j++)
            #pragma unroll
            for (int q = 0; q < 4; q++) acc[i][j][q] = 0.f;

    #pragma unroll
    for (int kc = 0; kc < 8; kc++) {
        const int c0 = kc * 16;
        float2 v[8];
        v[0] = *(const float2*)(rA0 + c0);
        v[1] = *(const float2*)(rA1 + c0);
        v[2] = *(const float2*)(rA2 + c0);
        v[3] = *(const float2*)(rA3 + c0);
        v[4] = *(const float2*)(rA0 + c0 + 8);
        v[5] = *(const float2*)(rA1 + c0 + 8);
        v[6] = *(const float2*)(rA2 + c0 + 8);
        v[7] = *(const float2*)(rA3 + c0 + 8);
        uint32_t ah0[4], ah1[4], al0[4], al1[4];
        split2(v[0].x, v[0].y, ah0[0], al0[0]);
        split2(v[1].x, v[1].y, ah0[1], al0[1]);
        split2(v[4].x, v[4].y, ah0[2], al0[2]);
        split2(v[5].x, v[5].y, ah0[3], al0[3]);
        split2(v[2].x, v[2].y, ah1[0], al1[0]);
        split2(v[3].x, v[3].y, ah1[1], al1[1]);
        split2(v[6].x, v[6].y, ah1[2], al1[2]);
        split2(v[7].x, v[7].y, ah1[3], al1[3]);

        const uint32_t kb = (uint32_t)kc * 32;
        #pragma unroll
        for (int g = 0; g < 4; g++) {
            uint32_t bh[4], bl[4];
            ldsm4(bh, b_hi + (uint32_t)g * 16 * TSTRIDE + kb);
            ldsm4(bl, b_lo + (uint32_t)g * 16 * TSTRIDE + kb);
            const int n0 = 2 * g, n1 = 2 * g + 1;
            mma_bf16(acc[0][n0], ah0, bh[0], bh[1]);
            mma_bf16(acc[0][n1], ah0, bh[2], bh[3]);
            mma_bf16(acc[1][n0], ah1, bh[0], bh[1]);
            mma_bf16(acc[1][n1], ah1, bh[2], bh[3]);
            mma_bf16(acc[0][n0], ah0, bl[0], bl[1]);
            mma_bf16(acc[0][n1], ah0, bl[2], bl[3]);
            mma_bf16(acc[1][n0], ah1, bl[0], bl[1]);
            mma_bf16(acc[1][n1], ah1, bl[2], bl[3]);
            mma_bf16(acc[0][n0], al0, bh[0], bh[1]);
            mma_bf16(acc[0][n1], al0, bh[2], bh[3]);
            mma_bf16(acc[1][n0], al1, bh[0], bh[1]);
            mma_bf16(acc[1][n1], al1, bh[2], bh[3]);
        }
    }

    __syncthreads();   // in-place safety (A may alias out)

    const float* sbias = (const float*)smem;
    #pragma unroll
    for (int mt = 0; mt < 2; mt++) {
        #pragma unroll
        for (int h = 0; h < 2; h++) {
            const int rloc = warp_m * 32 + mt * 16 + h * 8 + gid;
            if (rloc >= rvalid) continue;
            const int r = row0 + rloc;
            #pragma unroll
            for (int nt = 0; nt < 8; nt++) {
                const int col = warp_n * 64 + nt * 8 + 2 * tig;
                const float c0 = fmaxf(acc[mt][nt][h * 2 + 0] + sbias[col],     0.f);
                const float c1 = fmaxf(acc[mt][nt][h * 2 + 1] + sbias[col + 1], 0.f);
                if (OUTH)
                    *(__half2*)(outh + (size_t)r * DIM + col) = __floats2half2_rn(c0, c1);
                else
                    *(float2*)(outf + (size_t)r * DIM + col) = make_float2(c0, c1);
            }
        }
    }
}

// ==================== fp16-A GEMM, SAME bf16 3-pass MMA core =================
// A loaded as packed half pairs, split fp16->bf16 hi/lo in registers (exact).
// RELUOUT=true: out = relu(C+b) fp16 (enc2);  false: out = C fp16 (gcn hwh)
template <bool RELUOUT>
__global__ __launch_bounds__(256, 2)
void mmagemm16_kernel(const __half* __restrict__ A,
                      const __nv_bfloat16* __restrict__ Whi,
                      const __nv_bfloat16* __restrict__ Wlo,
                      const float* __restrict__ bias,
                      __half* __restrict__ out,
                      int nrows)
{
    extern __shared__ char smem[];
    const uint32_t sbase = smem_u32(smem);
    const int tid  = threadIdx.x;
    const int wid  = tid >> 5;
    const int lane = tid & 31;
    const int row0 = blockIdx.x * 128;
    const int rvalid = min(nrows - row0, 128);

    if (RELUOUT && tid < 128) ((float*)smem)[tid] = bias[tid];
    {
        const float4* sh = (const float4*)Whi;
        const float4* sl = (const float4*)Wlo;
        #pragma unroll
        for (int it = 0; it < 8; it++) {
            const int idx = tid + 256 * it;
            const int r = idx >> 4, c = idx & 15;
            *(float4*)(smem + BH_OFF + r * TSTRIDE + c * 16) = sh[idx];
            *(float4*)(smem + BL_OFF + r * TSTRIDE + c * 16) = sl[idx];
        }
    }
    __syncthreads();

    const int warp_m = wid & 3;
    const int warp_n = wid >> 2;
    const int gid = lane >> 2;
    const int tig = lane & 3;

    const int base = row0 + warp_m * 32 + gid;
    const __half* rA0 = A + (size_t)min(base +  0, nrows - 1) * DIM + tig * 2;
    const __half* rA1 = A + (size_t)min(base +  8, nrows - 1) * DIM + tig * 2;
    const __half* rA2 = A + (size_t)min(base + 16, nrows - 1) * DIM + tig * 2;
    const __half* rA3 = A + (size_t)min(base + 24, nrows - 1) * DIM + tig * 2;

    const uint32_t b_off = (uint32_t)(warp_n * 64 + (lane & 7) + (lane >> 4) * 8) * TSTRIDE
                         + (uint32_t)((lane >> 3) & 1) * 16;
    const uint32_t b_hi = sbase + BH_OFF + b_off;
    const uint32_t b_lo = sbase + BL_OFF + b_off;

    float acc[2][8][4];
    #pragma unroll
    for (int i = 0; i < 2; i++)
        #pragma unroll
        for (int j = 0; j < 8; j++)
            #pragma unroll
            for (int q = 0; q < 4; q++) acc[i][j][q] = 0.f;

    #pragma unroll
    for (int kc = 0; kc < 8; kc++) {
        const int c0 = kc * 16;
        uint32_t u[8];
        u[0] = *(const uint32_t*)(rA0 + c0);
        u[1] = *(const uint32_t*)(rA1 + c0);
        u[2] = *(const uint32_t*)(rA2 + c0);
        u[3] = *(const uint32_t*)(rA3 + c0);
        u[4] = *(const uint32_t*)(rA0 + c0 + 8);
        u[5] = *(const uint32_t*)(rA1 + c0 + 8);
        u[6] = *(const uint32_t*)(rA2 + c0 + 8);
        u[7] = *(const uint32_t*)(rA3 + c0 + 8);
        uint32_t ah0[4], ah1[4], al0[4], al1[4];
        split2h(u[0], ah0[0], al0[0]);
        split2h(u[1], ah0[1], al0[1]);
        split2h(u[4], ah0[2], al0[2]);
        split2h(u[5], ah0[3], al0[3]);
        split2h(u[2], ah1[0], al1[0]);
        split2h(u[3], ah1[1], al1[1]);
        split2h(u[6], ah1[2], al1[2]);
        split2h(u[7], ah1[3], al1[3]);

        const uint32_t kb = (uint32_t)kc * 32;
        #pragma unroll
        for (int g = 0; g < 4; g++) {
            uint32_t bh[4], bl[4];
            ldsm4(bh, b_hi + (uint32_t)g * 16 * TSTRIDE + kb);
            ldsm4(bl, b_lo + (uint32_t)g * 16 * TSTRIDE + kb);
            const int n0 = 2 * g, n1 = 2 * g + 1;
            mma_bf16(acc[0][n0], ah0, bh[0], bh[1]);
            mma_bf16(acc[0][n1], ah0, bh[2], bh[3]);
            mma_bf16(acc[1][n0], ah1, bh[0], bh[1]);
            mma_bf16(acc[1][n1], ah1, bh[2], bh[3]);
            mma_bf16(acc[0][n0], ah0, bl[0], bl[1]);
            mma_bf16(acc[0][n1], ah0, bl[2], bl[3]);
            mma_bf16(acc[1][n0], ah1, bl[0], bl[1]);
            mma_bf16(acc[1][n1], ah1, bl[2], bl[3]);
            mma_bf16(acc[0][n0], al0, bh[0], bh[1]);
            mma_bf16(acc[0][n1], al0, bh[2], bh[3]);
            mma_bf16(acc[1][n0], al1, bh[0], bh[1]);
            mma_bf16(acc[1][n1], al1, bh[2], bh[3]);
        }
    }

    __syncthreads();   // in-place safety (enc2: A aliases out)

    const float* sbias = (const float*)smem;
    #pragma unroll
    for (int mt = 0; mt < 2; mt++) {
        #pragma unroll
        for (int h = 0; h < 2; h++) {
            const int rloc = warp_m * 32 + mt * 16 + h * 8 + gid;
            if (rloc >= rvalid) continue;
            const int r = row0 + rloc;
            #pragma unroll
            for (int nt = 0; nt < 8; nt++) {
                const int col = warp_n * 64 + nt * 8 + 2 * tig;
                float c0 = acc[mt][nt][h * 2 + 0];
                float c1 = acc[mt][nt][h * 2 + 1];
                if (RELUOUT) {
                    c0 = fmaxf(c0 + sbias[col],     0.f);
                    c1 = fmaxf(c1 + sbias[col + 1], 0.f);
                }
                *(__half2*)(out + (size_t)r * DIM + col) = __floats2half2_rn(c0, c1);
            }
        }
    }
}

// ==================== gather: h = relu(agg), fp16 pure store =================
// h[n] = relu( inv[n]*Σ_{e∈CSR[n]} inv_s*hw16[s] + inv[n]^2*hw16[n] + b )
__global__ __launch_bounds__(256)
void gather_kernel(const __half* __restrict__ hwh, __half* __restrict__ hout,
                   const float* __restrict__ bias)
{
    const int node = (blockIdx.x * blockDim.x + threadIdx.x) >> 5;
    const int lane = threadIdx.x & 31;
    if (node >= NNODES) return;
    const int e0 = g_off[node];
    const int e1 = g_off[node + 1];

    float4 acc = make_float4(0.f, 0.f, 0.f, 0.f);
    int e = e0;
    for (; e + 2 <= e1; e += 2) {
        const int2 sw0 = g_csr[e];
        const int2 sw1 = g_csr[e + 1];
        const uint2 u0 = *((const uint2*)(hwh + (size_t)sw0.x * DIM) + lane);
        const uint2 u1 = *((const uint2*)(hwh + (size_t)sw1.x * DIM) + lane);
        const float w0 = __int_as_float(sw0.y);
        const float w1 = __int_as_float(sw1.y);
        float2 a0 = __half22float2(*(const __half2*)&u0.x);
        float2 b0 = __half22float2(*(const __half2*)&u0.y);
        float2 a1 = __half22float2(*(const __half2*)&u1.x);
        float2 b1 = __half22float2(*(const __half2*)&u1.y);
        acc.x = fmaf(a0.x, w0, acc.x); acc.y = fmaf(a0.y, w0, acc.y);
        acc.z = fmaf(b0.x, w0, acc.z); acc.w = fmaf(b0.y, w0, acc.w);
        acc.x = fmaf(a1.x, w1, acc.x); acc.y = fmaf(a1.y, w1, acc.y);
        acc.z = fmaf(b1.x, w1, acc.z); acc.w = fmaf(b1.y, w1, acc.w);
    }
    if (e < e1) {
        const int2 sw = g_csr[e];
        const uint2 u0 = *((const uint2*)(hwh + (size_t)sw.x * DIM) + lane);
        const float w = __int_as_float(sw.y);
        float2 a0 = __half22float2(*(const __half2*)&u0.x);
        float2 b0 = __half22float2(*(const __half2*)&u0.y);
        acc.x = fmaf(a0.x, w, acc.x); acc.y = fmaf(a0.y, w, acc.y);
        acc.z = fmaf(b0.x, w, acc.z); acc.w = fmaf(b0.y, w, acc.w);
    }

    const float invd = g_inv[node];
    const float sc   = invd * invd;
    const uint2 us = *((const uint2*)(hwh + (size_t)node * DIM) + lane);
    const float2 s0 = __half22float2(*(const __half2*)&us.x);
    const float2 s1 = __half22float2(*(const __half2*)&us.y);
    const float4 b  = *((const float4*)bias + lane);

    float4 a;
    a.x = fmaxf(fmaf(acc.x, invd, fmaf(s0.x, sc, b.x)), 0.f);
    a.y = fmaxf(fmaf(acc.y, invd, fmaf(s0.y, sc, b.y)), 0.f);
    a.z = fmaxf(fmaf(acc.z, invd, fmaf(s1.x, sc, b.z)), 0.f);
    a.w = fmaxf(fmaf(acc.w, invd, fmaf(s1.y, sc, b.w)), 0.f);
    const __half2 p0 = __floats2half2_rn(a.x, a.y);
    const __half2 p1 = __floats2half2_rn(a.z, a.w);
    uint2 st;
    st.x = *(const uint32_t*)&p0;
    st.y = *(const uint32_t*)&p1;
    *((uint2*)(hout + (size_t)node * DIM) + lane) = st;   // pure store
}

// ==================== pool: segment sums over fp16 h =========================
__global__ void gstart_kernel(const int* __restrict__ batch, int N) {
    const int g = blockIdx.x * blockDim.x + threadIdx.x;
    if (g > NGRAPH) return;
    if (g == NGRAPH) { g_gstart[NGRAPH] = N; return; }
    int lo = 0, hi = N;
    while (lo < hi) {
        int mid = (lo + hi) >> 1;
        if (batch[mid] < g) lo = mid + 1; else hi = mid;
    }
    g_gstart[g] = lo;
}

// 64 threads per graph block over half2 columns (keeps 4B loads per thread)
__global__ __launch_bounds__(64)
void pool_kernel(const __half* __restrict__ h)
{
    const int g = blockIdx.x;
    const int c = threadIdx.x;        // half2 column 0..63
    const int lo = g_gstart[g];
    const int hi = g_gstart[g + 1];
    float2 s = make_float2(0.f, 0.f);
    for (int i = lo; i < hi; i++) {
        const float2 v = __half22float2(((const __half2*)(h + (size_t)i * DIM))[c]);
        s.x += v.x; s.y += v.y;
    }
    *(float2*)(g_pool + (size_t)g * DIM + c * 2) = s;
}

__global__ void dec2_kernel(const float* __restrict__ dec1,
                            const float* __restrict__ W2,
                            const float* __restrict__ b2,
                            float* __restrict__ out)
{
    const int idx = blockIdx.x * blockDim.x + threadIdx.x;
    if (idx >= NGRAPH * OUTD) return;
    const int g = idx >> 5;
    const int o = idx & 31;
    const float* row = dec1 + (size_t)g * DIM;
    float s = b2[o];
    #pragma unroll 8
    for (int k = 0; k < DIM; k++) s = fmaf(row[k], W2[k * OUTD + o], s);
    out[idx] = s;
}

// ==================== host launch ===========================================
extern "C" void kernel_launch(void* const* d_in, const int* in_sizes, int n_in,
                              void* d_out, int out_size)
{
    const float* x       = (const float*)d_in[0];
    const int*   eidx    = (const int*)  d_in[1];
    const int*   batch   = (const int*)  d_in[2];
    const float* enc_W1  = (const float*)d_in[3];
    const float* enc_b1  = (const float*)d_in[4];
    const float* enc_W2  = (const float*)d_in[5];
    const float* enc_b2  = (const float*)d_in[6];
    const float* gcn_W   = (const float*)d_in[7];
    const float* gcn_b   = (const float*)d_in[8];
    const float* dec_W1  = (const float*)d_in[9];
    const float* dec_b1  = (const float*)d_in[10];
    const float* dec_W2  = (const float*)d_in[11];
    const float* dec_b2  = (const float*)d_in[12];

    const int N = in_sizes[0] / DIM;
    const int E = in_sizes[1] / 2;
    const int* src = eidx;
    const int* dst = eidx + E;

    float *poolp, *dec1p;
    __half *hp, *hwhp;
    int* cntp;
    __nv_bfloat16 *whip, *wlop;
    cudaGetSymbolAddress((void**)&hp,    g_h);
    cudaGetSymbolAddress((void**)&hwhp,  g_hwh);
    cudaGetSymbolAddress((void**)&poolp, g_pool);
    cudaGetSymbolAddress((void**)&dec1p, g_dec1);
    cudaGetSymbolAddress((void**)&cntp,  g_cnt);
    cudaGetSymbolAddress((void**)&whip,  g_whi);
    cudaGetSymbolAddress((void**)&wlop,  g_wlo);

    cudaFuncSetAttribute(mmagemm_kernel<true>,
                         cudaFuncAttributeMaxDynamicSharedMemorySize, SMEM_BYTES);
    cudaFuncSetAttribute(mmagemm_kernel<false>,
                         cudaFuncAttributeMaxDynamicSharedMemorySize, SMEM_BYTES);
    cudaFuncSetAttribute(mmagemm16_kernel<true>,
                         cudaFuncAttributeMaxDynamicSharedMemorySize, SMEM_BYTES);
    cudaFuncSetAttribute(mmagemm16_kernel<false>,
                         cudaFuncAttributeMaxDynamicSharedMemorySize, SMEM_BYTES);

    const int WSZ = DIM * DIM;
    const int gemm_blocks = (N + 127) / 128;

    // Fork a side stream for the CSR chain (independent of prep + encoder).
    cudaStream_t s2;
    cudaStreamCreateWithFlags(&s2, cudaStreamNonBlocking);
    cudaEvent_t ev_fork, ev_join;
    cudaEventCreateWithFlags(&ev_fork, cudaEventDisableTiming);
    cudaEventCreateWithFlags(&ev_join, cudaEventDisableTiming);

    cudaEventRecord(ev_fork, 0);
    cudaStreamWaitEvent(s2, ev_fork, 0);

    // ---- s2: CSR build + degree normalization + pool segment starts ----
    cudaMemsetAsync(cntp, 0, NNODES * sizeof(int), s2);
    hist_kernel<<<(E + 255) / 256, 256, 0, s2>>>(dst, E);
    invsqrt_kernel<<<(N + 255) / 256, 256, 0, s2>>>(N);
    blocksum_kernel<<<NBLK, 256, 0, s2>>>();
    bscan_kernel<<<1, 512, 0, s2>>>();
    offsets_kernel<<<NBLK, 256, 0, s2>>>();
    bin_kernel<<<(E + 255) / 256, 256, 0, s2>>>(src, dst, E);
    gstart_kernel<<<3, 256, 0, s2>>>(batch, N);
    cudaEventRecord(ev_join, s2);

    // ---- main stream: weight prep + encoder MLP ----
    {
        WPtrs wp;
        wp.w[0] = enc_W1; wp.w[1] = enc_W2;
        wp.w[2] = gcn_W;  wp.w[3] = gcn_W + WSZ; wp.w[4] = gcn_W + 2 * WSZ;
        wp.w[5] = dec_W1;
        prepw_kernel<<<NMAT * 64, 256>>>(wp);
    }
    // enc1: fp32 A (x) -> fp16 h, relu
    mmagemm_kernel<true><<<gemm_blocks, 256, SMEM_BYTES>>>(
        x, whip + 0 * WSZ, wlop + 0 * WSZ, enc_b1, nullptr, hp, N);
    // enc2: fp16 A -> fp16 h, relu (in place; sync-guarded); bf16 3-pass MMA
    mmagemm16_kernel<true><<<gemm_blocks, 256, SMEM_BYTES>>>(
        hp, whip + 1 * WSZ, wlop + 1 * WSZ, enc_b2, hp, N);

    // join: GCN gather needs g_inv/g_csr
    cudaStreamWaitEvent(0, ev_join, 0);

    // ---- GCN layers: fp16-A bf16-MMA GEMM -> hwh; gather -> relu'd fp16 h ----
    const int gather_blocks = (NNODES * 32 + 255) / 256;
    for (int l = 0; l < NLAYER; l++) {
        mmagemm16_kernel<false><<<gemm_blocks, 256, SMEM_BYTES>>>(
            hp, whip + (2 + l) * WSZ, wlop + (2 + l) * WSZ,
            nullptr, hwhp, N);
        gather_kernel<<<gather_blocks, 256>>>(hwhp, hp, gcn_b + (size_t)l * DIM);
    }

    // ---- global add pool + decoder ----
    pool_kernel<<<NGRAPH, 64>>>(hp);
    mmagemm_kernel<false><<<(NGRAPH + 127) / 128, 256, SMEM_BYTES>>>(
        poolp, whip + 5 * WSZ, wlop + 5 * WSZ, dec_b1, dec1p, nullptr, NGRAPH);
    dec2_kernel<<<(NGRAPH * OUTD + 255) / 256, 256>>>(dec1p, dec_W2, dec_b2, (float*)d_out);
}